// round 1
// baseline (speedup 1.0000x reference)
#include <cuda_runtime.h>
#include <math.h>

static constexpr int T_LEN = 4000000;
static constexpr int N4 = T_LEN / 4;          // float4 columns per row
static constexpr int RED_BLOCKS = 592;        // 4 per SM
static constexpr int RED_THREADS = 256;
static constexpr int XF_BLOCKS = 1184;
static constexpr int XF_THREADS = 256;

// Scratch (no device allocation allowed)
__device__ float g_part[RED_BLOCKS * 9];
__device__ float g_xf[12];   // B row-major (9) + c[3] where c = -B*refPos

// ---------------------------------------------------------------------------
// Pass 1: 9-way reduction over rows 0..2 of x:
//   s0..s2 = sum x_i ; s3..s8 = sum x_i*x_j (00,01,02,11,12,22)
// ---------------------------------------------------------------------------
__global__ void __launch_bounds__(RED_THREADS) reduce_kernel(const float* __restrict__ x) {
    const float4* __restrict__ r0 = (const float4*)(x);
    const float4* __restrict__ r1 = (const float4*)(x + T_LEN);
    const float4* __restrict__ r2 = (const float4*)(x + 2 * T_LEN);

    float s[9];
#pragma unroll
    for (int k = 0; k < 9; k++) s[k] = 0.0f;

    for (int i = blockIdx.x * blockDim.x + threadIdx.x; i < N4;
         i += gridDim.x * blockDim.x) {
        float4 a = r0[i], b = r1[i], c = r2[i];
        s[0] += (a.x + a.y) + (a.z + a.w);
        s[1] += (b.x + b.y) + (b.z + b.w);
        s[2] += (c.x + c.y) + (c.z + c.w);
        s[3] = fmaf(a.x, a.x, fmaf(a.y, a.y, fmaf(a.z, a.z, fmaf(a.w, a.w, s[3]))));
        s[4] = fmaf(a.x, b.x, fmaf(a.y, b.y, fmaf(a.z, b.z, fmaf(a.w, b.w, s[4]))));
        s[5] = fmaf(a.x, c.x, fmaf(a.y, c.y, fmaf(a.z, c.z, fmaf(a.w, c.w, s[5]))));
        s[6] = fmaf(b.x, b.x, fmaf(b.y, b.y, fmaf(b.z, b.z, fmaf(b.w, b.w, s[6]))));
        s[7] = fmaf(b.x, c.x, fmaf(b.y, c.y, fmaf(b.z, c.z, fmaf(b.w, c.w, s[7]))));
        s[8] = fmaf(c.x, c.x, fmaf(c.y, c.y, fmaf(c.z, c.z, fmaf(c.w, c.w, s[8]))));
    }

    // warp reduce
#pragma unroll
    for (int o = 16; o > 0; o >>= 1)
#pragma unroll
        for (int k = 0; k < 9; k++) s[k] += __shfl_down_sync(0xffffffffu, s[k], o);

    __shared__ float sw[RED_THREADS / 32][9];
    int warp = threadIdx.x >> 5, lane = threadIdx.x & 31;
    if (lane == 0)
#pragma unroll
        for (int k = 0; k < 9; k++) sw[warp][k] = s[k];
    __syncthreads();

    if (threadIdx.x < 9) {
        float t = 0.0f;
#pragma unroll
        for (int w = 0; w < RED_THREADS / 32; w++) t += sw[w][threadIdx.x];
        g_part[blockIdx.x * 9 + threadIdx.x] = t;
    }
}

// ---------------------------------------------------------------------------
// Pass 2: double-precision final reduce + 3x3 Jacobi eigensolver + basis build
// ---------------------------------------------------------------------------
__global__ void finalize_kernel(const float* __restrict__ x,
                                const float* __restrict__ axis) {
    __shared__ double swd[4][9];
    double loc[9];
#pragma unroll
    for (int k = 0; k < 9; k++) loc[k] = 0.0;
    for (int i = threadIdx.x; i < RED_BLOCKS; i += blockDim.x)
#pragma unroll
        for (int k = 0; k < 9; k++) loc[k] += (double)g_part[i * 9 + k];

#pragma unroll
    for (int o = 16; o > 0; o >>= 1)
#pragma unroll
        for (int k = 0; k < 9; k++) loc[k] += __shfl_down_sync(0xffffffffu, loc[k], o);

    int warp = threadIdx.x >> 5, lane = threadIdx.x & 31;
    if (lane == 0)
#pragma unroll
        for (int k = 0; k < 9; k++) swd[warp][k] = loc[k];
    __syncthreads();

    if (threadIdx.x != 0) return;

    double s[9];
#pragma unroll
    for (int k = 0; k < 9; k++)
        s[k] = swd[0][k] + swd[1][k] + swd[2][k] + swd[3][k];

    const double T = (double)T_LEN;
    // covariance: C[i][j] = (S_ij - S_i*S_j/T) / (T-1)
    double A[3][3];
    A[0][0] = (s[3] - s[0] * s[0] / T) / (T - 1.0);
    A[0][1] = (s[4] - s[0] * s[1] / T) / (T - 1.0);
    A[0][2] = (s[5] - s[0] * s[2] / T) / (T - 1.0);
    A[1][1] = (s[6] - s[1] * s[1] / T) / (T - 1.0);
    A[1][2] = (s[7] - s[1] * s[2] / T) / (T - 1.0);
    A[2][2] = (s[8] - s[2] * s[2] / T) / (T - 1.0);
    A[1][0] = A[0][1]; A[2][0] = A[0][2]; A[2][1] = A[1][2];

    // cyclic Jacobi, 10 sweeps (3x3 converges in ~3)
    double V[3][3] = {{1, 0, 0}, {0, 1, 0}, {0, 0, 1}};
    for (int sweep = 0; sweep < 10; sweep++) {
        const int PQ[3][2] = {{0, 1}, {0, 2}, {1, 2}};
        for (int r = 0; r < 3; r++) {
            int p = PQ[r][0], q = PQ[r][1];
            double apq = A[p][q];
            if (fabs(apq) < 1e-300) continue;
            double app = A[p][p], aqq = A[q][q];
            double phi = 0.5 * atan2(2.0 * apq, app - aqq);
            double c = cos(phi), sn = sin(phi);
            // A' = G^T A G with col_p(G)=(c,sn), col_q(G)=(-sn,c)
            double napp = c * c * app + 2.0 * c * sn * apq + sn * sn * aqq;
            double naqq = sn * sn * app - 2.0 * c * sn * apq + c * c * aqq;
            A[p][p] = napp; A[q][q] = naqq;
            A[p][q] = 0.0;  A[q][p] = 0.0;
            int o = 3 - p - q;  // the third index
            double aop = A[o][p], aoq = A[o][q];
            A[o][p] = c * aop + sn * aoq;  A[p][o] = A[o][p];
            A[o][q] = -sn * aop + c * aoq; A[q][o] = A[o][q];
            for (int rr = 0; rr < 3; rr++) {
                double vp = V[rr][p], vq = V[rr][q];
                V[rr][p] = c * vp + sn * vq;
                V[rr][q] = -sn * vp + c * vq;
            }
        }
    }

    // eigenvector of largest eigenvalue
    int kmax = 0;
    if (A[1][1] > A[kmax][kmax]) kmax = 1;
    if (A[2][2] > A[kmax][kmax]) kmax = 2;
    double z0 = V[0][kmax], z1 = V[1][kmax], z2 = V[2][kmax];

    // ZFwd = quat_vec_mul(Qrot, (0,0,1)); Qrot = x[3..6][t=0]
    double qx = (double)x[3 * T_LEN], qy = (double)x[4 * T_LEN];
    double qz = (double)x[5 * T_LEN], qw = (double)x[6 * T_LEN];
    double zf0 = 2.0 * (qx * qz + qw * qy);
    double zf1 = 2.0 * (qy * qz - qw * qx);
    double zf2 = 1.0 - 2.0 * (qx * qx + qy * qy);
    if (zf0 * z0 + zf1 * z1 + zf2 * z2 < 0.0) { z0 = -z0; z1 = -z1; z2 = -z2; }

    double u0 = (double)axis[0], u1 = (double)axis[1], u2 = (double)axis[2];
    // right = cross(up, z)
    double r0 = u1 * z2 - u2 * z1;
    double r1 = u2 * z0 - u0 * z2;
    double r2 = u0 * z1 - u1 * z0;
    // fwd = cross(right, up)
    double f0 = r1 * u2 - r2 * u1;
    double f1 = r2 * u0 - r0 * u2;
    double f2 = r0 * u1 - r1 * u0;

    double B[3][3] = {{r0, r1, r2}, {u0, u1, u2}, {f0, f1, f2}};
    double rp0 = (double)x[0], rp1 = (double)x[T_LEN], rp2 = (double)x[2 * T_LEN];

    for (int i = 0; i < 3; i++)
        for (int j = 0; j < 3; j++) g_xf[i * 3 + j] = (float)B[i][j];
    g_xf[9]  = (float)(-(B[0][0] * rp0 + B[0][1] * rp1 + B[0][2] * rp2));
    g_xf[10] = (float)(-(B[1][0] * rp0 + B[1][1] * rp1 + B[1][2] * rp2));
    g_xf[11] = (float)(-(B[2][0] * rp0 + B[2][1] * rp1 + B[2][2] * rp2));
}

// ---------------------------------------------------------------------------
// Pass 3: out[0:3] = B*(Xpos - refPos); out[3:6] = x[7:10] (copy)
// ---------------------------------------------------------------------------
__global__ void __launch_bounds__(XF_THREADS) transform_kernel(
    const float* __restrict__ x, float* __restrict__ out) {
    const float b00 = g_xf[0], b01 = g_xf[1], b02 = g_xf[2];
    const float b10 = g_xf[3], b11 = g_xf[4], b12 = g_xf[5];
    const float b20 = g_xf[6], b21 = g_xf[7], b22 = g_xf[8];
    const float c0 = g_xf[9], c1 = g_xf[10], c2 = g_xf[11];

    const float4* __restrict__ r0 = (const float4*)(x);
    const float4* __restrict__ r1 = (const float4*)(x + T_LEN);
    const float4* __restrict__ r2 = (const float4*)(x + 2 * T_LEN);
    const float4* __restrict__ a0 = (const float4*)(x + 7 * T_LEN);
    const float4* __restrict__ a1 = (const float4*)(x + 8 * T_LEN);
    const float4* __restrict__ a2 = (const float4*)(x + 9 * T_LEN);
    float4* __restrict__ o0 = (float4*)(out);
    float4* __restrict__ o1 = (float4*)(out + T_LEN);
    float4* __restrict__ o2 = (float4*)(out + 2 * T_LEN);
    float4* __restrict__ o3 = (float4*)(out + 3 * T_LEN);
    float4* __restrict__ o4 = (float4*)(out + 4 * T_LEN);
    float4* __restrict__ o5 = (float4*)(out + 5 * T_LEN);

    for (int i = blockIdx.x * blockDim.x + threadIdx.x; i < N4;
         i += gridDim.x * blockDim.x) {
        float4 p0 = r0[i], p1 = r1[i], p2 = r2[i];
        float4 q0, q1, q2;
        q0.x = fmaf(b00, p0.x, fmaf(b01, p1.x, fmaf(b02, p2.x, c0)));
        q0.y = fmaf(b00, p0.y, fmaf(b01, p1.y, fmaf(b02, p2.y, c0)));
        q0.z = fmaf(b00, p0.z, fmaf(b01, p1.z, fmaf(b02, p2.z, c0)));
        q0.w = fmaf(b00, p0.w, fmaf(b01, p1.w, fmaf(b02, p2.w, c0)));
        q1.x = fmaf(b10, p0.x, fmaf(b11, p1.x, fmaf(b12, p2.x, c1)));
        q1.y = fmaf(b10, p0.y, fmaf(b11, p1.y, fmaf(b12, p2.y, c1)));
        q1.z = fmaf(b10, p0.z, fmaf(b11, p1.z, fmaf(b12, p2.z, c1)));
        q1.w = fmaf(b10, p0.w, fmaf(b11, p1.w, fmaf(b12, p2.w, c1)));
        q2.x = fmaf(b20, p0.x, fmaf(b21, p1.x, fmaf(b22, p2.x, c2)));
        q2.y = fmaf(b20, p0.y, fmaf(b21, p1.y, fmaf(b22, p2.y, c2)));
        q2.z = fmaf(b20, p0.z, fmaf(b21, p1.z, fmaf(b22, p2.z, c2)));
        q2.w = fmaf(b20, p0.w, fmaf(b21, p1.w, fmaf(b22, p2.w, c2)));
        o0[i] = q0; o1[i] = q1; o2[i] = q2;
        o3[i] = a0[i]; o4[i] = a1[i]; o5[i] = a2[i];
    }
}

extern "C" void kernel_launch(void* const* d_in, const int* in_sizes, int n_in,
                              void* d_out, int out_size) {
    const float* x = (const float*)d_in[0];
    const float* axis = (const float*)d_in[1];
    float* out = (float*)d_out;

    reduce_kernel<<<RED_BLOCKS, RED_THREADS>>>(x);
    finalize_kernel<<<1, 128>>>(x, axis);
    transform_kernel<<<XF_BLOCKS, XF_THREADS>>>(x, out);
}

// round 2
// speedup vs baseline: 1.0747x; 1.0747x over previous
#include <cuda_runtime.h>
#include <math.h>

static constexpr int T_LEN = 4000000;
static constexpr int N4 = T_LEN / 4;          // float4 columns per row
static constexpr int RED_BLOCKS = 1184;       // 8 per SM
static constexpr int RED_THREADS = 256;
static constexpr int XF_THREADS = 256;
static constexpr int XF_BLOCKS = (N4 + XF_THREADS - 1) / XF_THREADS;

// Scratch (no device allocation allowed)
__device__ float g_part[RED_BLOCKS * 9];
__device__ float g_xf[12];   // B row-major (9) + c[3] where c = -B*refPos

// ---------------------------------------------------------------------------
// Pass 1: 9-way reduction over rows 0..2 of x  PLUS  copy rows 7..9 -> out 3..5
//   s0..s2 = sum x_i ; s3..s8 = sum x_i*x_j (00,01,02,11,12,22)
// Copy path uses streaming hints so it does not evict rows 0..2 from L2
// (transform kernel re-reads them).
// ---------------------------------------------------------------------------
__global__ void __launch_bounds__(RED_THREADS) reduce_copy_kernel(
    const float* __restrict__ x, float* __restrict__ out) {
    const float4* __restrict__ r0 = (const float4*)(x);
    const float4* __restrict__ r1 = (const float4*)(x + T_LEN);
    const float4* __restrict__ r2 = (const float4*)(x + 2 * T_LEN);
    const float4* __restrict__ a0 = (const float4*)(x + 7 * T_LEN);
    const float4* __restrict__ a1 = (const float4*)(x + 8 * T_LEN);
    const float4* __restrict__ a2 = (const float4*)(x + 9 * T_LEN);
    float4* __restrict__ o3 = (float4*)(out + 3 * T_LEN);
    float4* __restrict__ o4 = (float4*)(out + 4 * T_LEN);
    float4* __restrict__ o5 = (float4*)(out + 5 * T_LEN);

    float s[9];
#pragma unroll
    for (int k = 0; k < 9; k++) s[k] = 0.0f;

    for (int i = blockIdx.x * blockDim.x + threadIdx.x; i < N4;
         i += gridDim.x * blockDim.x) {
        float4 a = r0[i], b = r1[i], c = r2[i];
        // streaming copy (evict-first both sides)
        float4 u = __ldcs(&a0[i]);
        float4 v = __ldcs(&a1[i]);
        float4 w = __ldcs(&a2[i]);
        __stcs(&o3[i], u);
        __stcs(&o4[i], v);
        __stcs(&o5[i], w);

        s[0] += (a.x + a.y) + (a.z + a.w);
        s[1] += (b.x + b.y) + (b.z + b.w);
        s[2] += (c.x + c.y) + (c.z + c.w);
        s[3] = fmaf(a.x, a.x, fmaf(a.y, a.y, fmaf(a.z, a.z, fmaf(a.w, a.w, s[3]))));
        s[4] = fmaf(a.x, b.x, fmaf(a.y, b.y, fmaf(a.z, b.z, fmaf(a.w, b.w, s[4]))));
        s[5] = fmaf(a.x, c.x, fmaf(a.y, c.y, fmaf(a.z, c.z, fmaf(a.w, c.w, s[5]))));
        s[6] = fmaf(b.x, b.x, fmaf(b.y, b.y, fmaf(b.z, b.z, fmaf(b.w, b.w, s[6]))));
        s[7] = fmaf(b.x, c.x, fmaf(b.y, c.y, fmaf(b.z, c.z, fmaf(b.w, c.w, s[7]))));
        s[8] = fmaf(c.x, c.x, fmaf(c.y, c.y, fmaf(c.z, c.z, fmaf(c.w, c.w, s[8]))));
    }

    // warp reduce
#pragma unroll
    for (int o = 16; o > 0; o >>= 1)
#pragma unroll
        for (int k = 0; k < 9; k++) s[k] += __shfl_down_sync(0xffffffffu, s[k], o);

    __shared__ float sw[RED_THREADS / 32][9];
    int warp = threadIdx.x >> 5, lane = threadIdx.x & 31;
    if (lane == 0)
#pragma unroll
        for (int k = 0; k < 9; k++) sw[warp][k] = s[k];
    __syncthreads();

    if (threadIdx.x < 9) {
        float t = 0.0f;
#pragma unroll
        for (int w = 0; w < RED_THREADS / 32; w++) t += sw[w][threadIdx.x];
        g_part[blockIdx.x * 9 + threadIdx.x] = t;
    }
}

// ---------------------------------------------------------------------------
// Pass 2: double-precision final reduce + sqrt-based 3x3 Jacobi + basis build.
// NO double transcendentals (atan2/sin/cos) -- those cost ~tens of us serial.
// ---------------------------------------------------------------------------
__global__ void finalize_kernel(const float* __restrict__ x,
                                const float* __restrict__ axis) {
    __shared__ double swd[8][9];
    double loc[9];
#pragma unroll
    for (int k = 0; k < 9; k++) loc[k] = 0.0;
    for (int i = threadIdx.x; i < RED_BLOCKS; i += blockDim.x)
#pragma unroll
        for (int k = 0; k < 9; k++) loc[k] += (double)g_part[i * 9 + k];

#pragma unroll
    for (int o = 16; o > 0; o >>= 1)
#pragma unroll
        for (int k = 0; k < 9; k++) loc[k] += __shfl_down_sync(0xffffffffu, loc[k], o);

    int warp = threadIdx.x >> 5, lane = threadIdx.x & 31;
    if (lane == 0)
#pragma unroll
        for (int k = 0; k < 9; k++) swd[warp][k] = loc[k];
    __syncthreads();

    if (threadIdx.x != 0) return;

    double s[9];
#pragma unroll
    for (int k = 0; k < 9; k++) {
        double t = 0.0;
#pragma unroll
        for (int w = 0; w < 8; w++) t += swd[w][k];
        s[k] = t;
    }

    const double T = (double)T_LEN;
    // covariance: C[i][j] = (S_ij - S_i*S_j/T) / (T-1)
    double A[3][3];
    A[0][0] = (s[3] - s[0] * s[0] / T) / (T - 1.0);
    A[0][1] = (s[4] - s[0] * s[1] / T) / (T - 1.0);
    A[0][2] = (s[5] - s[0] * s[2] / T) / (T - 1.0);
    A[1][1] = (s[6] - s[1] * s[1] / T) / (T - 1.0);
    A[1][2] = (s[7] - s[1] * s[2] / T) / (T - 1.0);
    A[2][2] = (s[8] - s[2] * s[2] / T) / (T - 1.0);
    A[1][0] = A[0][1]; A[2][0] = A[0][2]; A[2][1] = A[1][2];

    // cyclic Jacobi, sqrt-only rotations (Golub & Van Loan 8.4)
    double V[3][3] = {{1, 0, 0}, {0, 1, 0}, {0, 0, 1}};
    for (int sweep = 0; sweep < 8; sweep++) {
        const int PQ[3][2] = {{0, 1}, {0, 2}, {1, 2}};
        for (int r = 0; r < 3; r++) {
            int p = PQ[r][0], q = PQ[r][1];
            double apq = A[p][q];
            if (apq == 0.0) continue;
            double theta = (A[q][q] - A[p][p]) / (2.0 * apq);
            double t = 1.0 / (fabs(theta) + sqrt(theta * theta + 1.0));
            if (theta < 0.0) t = -t;
            double c = 1.0 / sqrt(t * t + 1.0);
            double sn = t * c;
            // A' = J^T A J,  J[p][p]=c, J[q][q]=c, J[p][q]=sn, J[q][p]=-sn
            A[p][p] -= t * apq;
            A[q][q] += t * apq;
            A[p][q] = 0.0; A[q][p] = 0.0;
            int o = 3 - p - q;  // the third index
            double aop = A[o][p], aoq = A[o][q];
            A[o][p] = c * aop - sn * aoq;  A[p][o] = A[o][p];
            A[o][q] = sn * aop + c * aoq;  A[q][o] = A[o][q];
            for (int rr = 0; rr < 3; rr++) {
                double vp = V[rr][p], vq = V[rr][q];
                V[rr][p] = c * vp - sn * vq;
                V[rr][q] = sn * vp + c * vq;
            }
        }
    }

    // eigenvector of largest eigenvalue
    int kmax = 0;
    if (A[1][1] > A[kmax][kmax]) kmax = 1;
    if (A[2][2] > A[kmax][kmax]) kmax = 2;
    double z0 = V[0][kmax], z1 = V[1][kmax], z2 = V[2][kmax];

    // ZFwd = quat_vec_mul(Qrot, (0,0,1)); Qrot = x[3..6][t=0]
    double qx = (double)x[3 * T_LEN], qy = (double)x[4 * T_LEN];
    double qz = (double)x[5 * T_LEN], qw = (double)x[6 * T_LEN];
    double zf0 = 2.0 * (qx * qz + qw * qy);
    double zf1 = 2.0 * (qy * qz - qw * qx);
    double zf2 = 1.0 - 2.0 * (qx * qx + qy * qy);
    if (zf0 * z0 + zf1 * z1 + zf2 * z2 < 0.0) { z0 = -z0; z1 = -z1; z2 = -z2; }

    double u0 = (double)axis[0], u1 = (double)axis[1], u2 = (double)axis[2];
    // right = cross(up, z)
    double r0 = u1 * z2 - u2 * z1;
    double r1 = u2 * z0 - u0 * z2;
    double r2 = u0 * z1 - u1 * z0;
    // fwd = cross(right, up)
    double f0 = r1 * u2 - r2 * u1;
    double f1 = r2 * u0 - r0 * u2;
    double f2 = r0 * u1 - r1 * u0;

    double B[3][3] = {{r0, r1, r2}, {u0, u1, u2}, {f0, f1, f2}};
    double rp0 = (double)x[0], rp1 = (double)x[T_LEN], rp2 = (double)x[2 * T_LEN];

    for (int i = 0; i < 3; i++)
        for (int j = 0; j < 3; j++) g_xf[i * 3 + j] = (float)B[i][j];
    g_xf[9]  = (float)(-(B[0][0] * rp0 + B[0][1] * rp1 + B[0][2] * rp2));
    g_xf[10] = (float)(-(B[1][0] * rp0 + B[1][1] * rp1 + B[1][2] * rp2));
    g_xf[11] = (float)(-(B[2][0] * rp0 + B[2][1] * rp1 + B[2][2] * rp2));
}

// ---------------------------------------------------------------------------
// Pass 3: out[0:3] = B*(Xpos - refPos).  Rows 0..2 should be L2-resident from
// pass 1. Stores are streaming (never re-read).
// ---------------------------------------------------------------------------
__global__ void __launch_bounds__(XF_THREADS) transform_kernel(
    const float* __restrict__ x, float* __restrict__ out) {
    const int i = blockIdx.x * blockDim.x + threadIdx.x;
    if (i >= N4) return;

    const float b00 = g_xf[0], b01 = g_xf[1], b02 = g_xf[2];
    const float b10 = g_xf[3], b11 = g_xf[4], b12 = g_xf[5];
    const float b20 = g_xf[6], b21 = g_xf[7], b22 = g_xf[8];
    const float c0 = g_xf[9], c1 = g_xf[10], c2 = g_xf[11];

    const float4* __restrict__ r0 = (const float4*)(x);
    const float4* __restrict__ r1 = (const float4*)(x + T_LEN);
    const float4* __restrict__ r2 = (const float4*)(x + 2 * T_LEN);
    float4* __restrict__ o0 = (float4*)(out);
    float4* __restrict__ o1 = (float4*)(out + T_LEN);
    float4* __restrict__ o2 = (float4*)(out + 2 * T_LEN);

    float4 p0 = r0[i], p1 = r1[i], p2 = r2[i];
    float4 q0, q1, q2;
    q0.x = fmaf(b00, p0.x, fmaf(b01, p1.x, fmaf(b02, p2.x, c0)));
    q0.y = fmaf(b00, p0.y, fmaf(b01, p1.y, fmaf(b02, p2.y, c0)));
    q0.z = fmaf(b00, p0.z, fmaf(b01, p1.z, fmaf(b02, p2.z, c0)));
    q0.w = fmaf(b00, p0.w, fmaf(b01, p1.w, fmaf(b02, p2.w, c0)));
    q1.x = fmaf(b10, p0.x, fmaf(b11, p1.x, fmaf(b12, p2.x, c1)));
    q1.y = fmaf(b10, p0.y, fmaf(b11, p1.y, fmaf(b12, p2.y, c1)));
    q1.z = fmaf(b10, p0.z, fmaf(b11, p1.z, fmaf(b12, p2.z, c1)));
    q1.w = fmaf(b10, p0.w, fmaf(b11, p1.w, fmaf(b12, p2.w, c1)));
    q2.x = fmaf(b20, p0.x, fmaf(b21, p1.x, fmaf(b22, p2.x, c2)));
    q2.y = fmaf(b20, p0.y, fmaf(b21, p1.y, fmaf(b22, p2.y, c2)));
    q2.z = fmaf(b20, p0.z, fmaf(b21, p1.z, fmaf(b22, p2.z, c2)));
    q2.w = fmaf(b20, p0.w, fmaf(b21, p1.w, fmaf(b22, p2.w, c2)));
    __stcs(&o0[i], q0);
    __stcs(&o1[i], q1);
    __stcs(&o2[i], q2);
}

extern "C" void kernel_launch(void* const* d_in, const int* in_sizes, int n_in,
                              void* d_out, int out_size) {
    const float* x = (const float*)d_in[0];
    const float* axis = (const float*)d_in[1];
    float* out = (float*)d_out;

    reduce_copy_kernel<<<RED_BLOCKS, RED_THREADS>>>(x, out);
    finalize_kernel<<<1, 256>>>(x, axis);
    transform_kernel<<<XF_BLOCKS, XF_THREADS>>>(x, out);
}